// round 11
// baseline (speedup 1.0000x reference)
#include <cuda_runtime.h>
#include <cstdint>

#define BATCH 128
#define PATCHES 196
#define FEAT 784
#define H1 64
#define NOUT 10

#define CLUSTER 4
#define ROWS_PER_CTA (H1 / CLUSTER)        // 16 weight rows copied per CTA

#define W_STRIDE 788                       // floats per padded weight row (784+4)
#define SMEM_W_BYTES (H1 * W_STRIDE * 4)   // 201728

// smem byte offsets
#define OFF_W      0
#define OFF_FEAT   (SMEM_W_BYTES)              // 784 floats
#define OFF_PART   (OFF_FEAT + FEAT * 4)       // 8*64 floats
#define OFF_H      (OFF_PART + 8 * H1 * 4)     // 64 floats
#define OFF_CW     (OFF_H + H1 * 4)            // 12 floats
#define OFF_SW     (OFF_CW + 12 * 4)           // 12 floats
#define OFF_AB     (OFF_SW + 12 * 4)           // 48 floats
#define OFF_OBS    (OFF_AB + 48 * 4)           // 12 floats
#define OFF_C      (OFF_OBS + 12 * 4)          // 4*81 = 324 floats (coef tensor)
#define OFF_MBAR   (OFF_C + 324 * 4)           // 8 bytes (8-aligned: 1296%8==0)
#define SMEM_TOTAL (OFF_MBAR + 16)

__device__ __forceinline__ uint32_t saddr(const void* p) {
    return (uint32_t)__cvta_generic_to_shared(p);
}

// ---------------------------------------------------------------------------
// Full folded circuit for one set of per-qubit half-angle (c,s) pairs.
// Identical math to the verified per-patch circuit from previous rounds.
// ---------------------------------------------------------------------------
__device__ __forceinline__ void eval_circuit(
    const float* c4, const float* s4,
    const float* cw, const float* sw, const float* ab, const float* obs,
    float* e_out)
{
    // per-qubit 2-amp states through Rx + layer-0 folded-in-parts
    float a0r[4], a0i[4], a1r[4], a1i[4];
#pragma unroll
    for (int q = 0; q < 4; q++) {
        float c = c4[q], s = s4[q];
        float xr0 = c,    xi0 = 0.0f;
        float xr1 = 0.0f, xi1 = -s;
        float c1 = cw[q], s1 = sw[q];
        float yr0 = c1*xr0 - s1*xr1, yi0 = c1*xi0 - s1*xi1;
        float yr1 = s1*xr0 + c1*xr1, yi1 = s1*xi0 + c1*xi1;
        float c2 = cw[4+q], s2 = sw[4+q];
        float zr0 = yr0*c2 + yi0*s2, zi0 = yi0*c2 - yr0*s2;
        float zr1 = yr1*c2 - yi1*s2, zi1 = yi1*c2 + yr1*s2;
        float c3 = cw[8+q], s3 = sw[8+q];
        a0r[q] = c3*zr0 - s3*zr1;  a0i[q] = c3*zi0 - s3*zi1;
        a1r[q] = s3*zr0 + c3*zr1;  a1i[q] = s3*zi0 + c3*zi1;
    }

    // tensor up to 16 amps
    float ur[4], ui[4], vr[4], vi[4];
#pragma unroll
    for (int i0 = 0; i0 < 2; i0++)
#pragma unroll
        for (int i1 = 0; i1 < 2; i1++) {
            float xr = i0 ? a1r[0] : a0r[0], xi = i0 ? a1i[0] : a0i[0];
            float yr = i1 ? a1r[1] : a0r[1], yi = i1 ? a1i[1] : a0i[1];
            ur[i0*2+i1] = xr*yr - xi*yi;
            ui[i0*2+i1] = xr*yi + xi*yr;
            float zr = i0 ? a1r[2] : a0r[2], zi = i0 ? a1i[2] : a0i[2];
            float wr2 = i1 ? a1r[3] : a0r[3], wi2 = i1 ? a1i[3] : a0i[3];
            vr[i0*2+i1] = zr*wr2 - zi*wi2;
            vi[i0*2+i1] = zr*wi2 + zi*wr2;
        }
    float sr[16], si[16];
#pragma unroll
    for (int k = 0; k < 16; k++) {
        float xr = ur[k >> 2], xi = ui[k >> 2];
        float yr = vr[k & 3],  yi = vi[k & 3];
        sr[k] = xr*yr - xi*yi;
        si[k] = xr*yi + xi*yr;
    }

    // ring CNOTs after layer 0
#pragma unroll
    for (int q = 0; q < 4; q++) {
        int cmask = 1 << (3 - q);
        int tmask = 1 << (3 - ((q + 1) & 3));
#pragma unroll
        for (int k = 0; k < 16; k++) {
            if ((k & cmask) && !(k & tmask)) {
                int k1 = k | tmask;
                float tr = sr[k]; sr[k] = sr[k1]; sr[k1] = tr;
                float ti = si[k]; si[k] = si[k1]; si[k1] = ti;
            }
        }
    }

    // layers 1..3: folded SU(2) gate per qubit, then ring
#pragma unroll
    for (int l = 0; l < 3; l++) {
#pragma unroll
        for (int q = 0; q < 4; q++) {
            const float* o = ab + (l * 4 + q) * 4;
            float Ar = o[0], Ai = o[1], Br = o[2], Bi = o[3];
            int st = 1 << (3 - q);
#pragma unroll
            for (int k = 0; k < 16; k++) {
                if (k & st) continue;
                int k1 = k | st;
                float r0 = sr[k],  i0v = si[k];
                float r1 = sr[k1], i1v = si[k1];
                sr[k]  = Ar*r0 - Ai*i0v - Br*r1 - Bi*i1v;
                si[k]  = Ar*i0v + Ai*r0 - Br*i1v + Bi*r1;
                sr[k1] = Br*r0 - Bi*i0v + Ar*r1 + Ai*i1v;
                si[k1] = Br*i0v + Bi*r0 + Ar*i1v - Ai*r1;
            }
        }
#pragma unroll
        for (int q = 0; q < 4; q++) {
            int cmask = 1 << (3 - q);
            int tmask = 1 << (3 - ((q + 1) & 3));
#pragma unroll
            for (int k = 0; k < 16; k++) {
                if ((k & cmask) && !(k & tmask)) {
                    int k1 = k | tmask;
                    float tr = sr[k]; sr[k] = sr[k1]; sr[k1] = tr;
                    float ti = si[k]; si[k] = si[k1]; si[k1] = ti;
                }
            }
        }
    }

    // layer 4 + <Z_q> folded observable
    float p[16];
#pragma unroll
    for (int k = 0; k < 16; k++) p[k] = sr[k]*sr[k] + si[k]*si[k];
#pragma unroll
    for (int q = 0; q < 4; q++) {
        int st = 1 << (3 - q);
        float A  = obs[q * 3 + 0];
        float BR = obs[q * 3 + 1];
        float BI = obs[q * 3 + 2];
        float e = 0.0f;
#pragma unroll
        for (int k = 0; k < 16; k++) {
            if (k & st) continue;
            int k1 = k | st;
            float X = sr[k]*sr[k1] + si[k]*si[k1];
            float Y = sr[k]*si[k1] - si[k]*sr[k1];
            e += A * (p[k] - p[k1]) + BR * X - BI * Y;
        }
        e_out[q] = e;
    }
}

__global__ void __launch_bounds__(512) __cluster_dims__(CLUSTER, 1, 1)
fused_kernel(
    const float* __restrict__ x, const float* __restrict__ w,
    const float* __restrict__ fc1_w, const float* __restrict__ fc1_b,
    const float* __restrict__ fc2_w, const float* __restrict__ fc2_b,
    float* __restrict__ out)
{
    extern __shared__ char smem[];
    float* wsm    = (float*)(smem + OFF_W);
    float* feat_s = (float*)(smem + OFF_FEAT);
    float* part_s = (float*)(smem + OFF_PART);
    float* h_s    = (float*)(smem + OFF_H);
    float* cw     = (float*)(smem + OFF_CW);
    float* sw     = (float*)(smem + OFF_SW);
    float* ab     = (float*)(smem + OFF_AB);
    float* obs    = (float*)(smem + OFF_OBS);
    float* Csm    = (float*)(smem + OFF_C);
    uint32_t mbar = saddr(smem + OFF_MBAR);

    int b = blockIdx.x;
    int t = threadIdx.x;

    // ---- prefetch per-patch pixels early (used only in the contraction) ----
    float px0 = 0.f, px1 = 0.f, px2 = 0.f, px3 = 0.f;
    if (t < PATCHES) {
        int i = t / 14, j = t % 14;
        const float* xb = x + b * FEAT;
        px0 = xb[(2*i)  *28 + 2*j    ];
        px1 = xb[(2*i)  *28 + 2*j + 1];
        px2 = xb[(2*i+1)*28 + 2*j    ];
        px3 = xb[(2*i+1)*28 + 2*j + 1];
    }

    // ---- per-block precompute of folded gates ----
    if (t < 12) {
        float s, c;
        __sincosf(0.5f * w[t], &s, &c);
        cw[t] = c; sw[t] = s;
    } else if (t >= 32 && t < 44) {     // layers 1..3 folded SU(2)
        int idx = t - 32;
        int l = idx >> 2, q = idx & 3;
        int base = (l + 1) * 12;
        float c1, s1, c2, s2, c3, s3;
        __sincosf(0.5f * w[base + q],     &s1, &c1);
        __sincosf(0.5f * w[base + 4 + q], &s2, &c2);
        __sincosf(0.5f * w[base + 8 + q], &s3, &c3);
        float* o = ab + idx * 4;
        o[0] =  c2 * (c3 * c1 - s3 * s1);
        o[1] = -s2 * (c3 * c1 + s3 * s1);
        o[2] =  c2 * (s3 * c1 + c3 * s1);
        o[3] =  s2 * (c3 * s1 - s3 * c1);
    } else if (t >= 64 && t < 68) {     // layer-4 + <Z_q> observable
        int q = t - 64;
        float c1, s1, c2, s2, c3, s3;
        __sincosf(0.5f * w[48 + q], &s1, &c1);
        __sincosf(0.5f * w[52 + q], &s2, &c2);
        __sincosf(0.5f * w[56 + q], &s3, &c3);
        float ar =  c2 * (c3 * c1 - s3 * s1);
        float ai = -s2 * (c3 * c1 + s3 * s1);
        float br =  c2 * (s3 * c1 + c3 * s1);
        float bi =  s2 * (c3 * s1 - s3 * c1);
        obs[q * 3 + 0] = ar * ar + ai * ai - br * br - bi * bi;
        obs[q * 3 + 1] = 4.0f * (ai * bi - ar * br);
        obs[q * 3 + 2] = 4.0f * (ar * bi + ai * br);
    } else if (t == 511) {
        asm volatile("mbarrier.init.shared.b64 [%0], 1;" :: "r"(mbar) : "memory");
    }
    __syncthreads();

    // ---- cluster-wide: barriers ready before any multicast lands ----
    asm volatile("barrier.cluster.arrive.aligned;" ::: "memory");
    asm volatile("barrier.cluster.wait.aligned;"   ::: "memory");

    // ---- kick off fc1_w -> smem multicast copy (overlaps phases 0/1) ----
    if (t == 511) {
        uint32_t rank;
        asm("mov.u32 %0, %%cluster_ctarank;" : "=r"(rank));
        asm volatile("mbarrier.arrive.expect_tx.shared.b64 _, [%0], %1;"
                     :: "r"(mbar), "r"((uint32_t)(H1 * 3136u)) : "memory");
        const uint16_t mask = (1u << CLUSTER) - 1u;
        int row0 = rank * ROWS_PER_CTA;
        for (int n = row0; n < row0 + ROWS_PER_CTA; n++) {
            uint32_t dst = saddr(wsm + n * W_STRIDE);
            const float* src = fc1_w + n * FEAT;
            asm volatile(
                "cp.async.bulk.shared::cluster.global.mbarrier::complete_tx::bytes"
                ".multicast::cluster [%0], [%1], %2, [%3], %4;"
                :: "r"(dst), "l"(src), "r"(3136u), "r"(mbar), "h"(mask) : "memory");
        }
    }

    // =====================================================================
    // Phase 0: evaluate circuit at 81 node-angle combos (a in {0, pi, pi/2}).
    // Half-angle (c,s): d=0 -> (1,0); d=1 -> (0,1); d=2 -> (r2,r2).
    // E[q][node] written into Csm (transformed in-place below).
    // =====================================================================
    if (t < 81) {
        const float R2 = 0.70710678118654752f;
        int d0 = t / 27, r = t % 27;
        int d1 = r / 9, d2 = (r / 3) % 3, d3 = r % 3;
        int dg[4] = {d0, d1, d2, d3};
        float c4[4], s4[4];
#pragma unroll
        for (int q = 0; q < 4; q++) {
            int d = dg[q];
            c4[q] = (d == 0) ? 1.0f : (d == 1) ? 0.0f : R2;
            s4[q] = (d == 0) ? 0.0f : (d == 1) ? 1.0f : R2;
        }
        float e[4];
        eval_circuit(c4, s4, cw, sw, ab, obs, e);
#pragma unroll
        for (int q = 0; q < 4; q++) Csm[q * 81 + t] = e[q];
    }
    __syncthreads();

    // =====================================================================
    // Transform: per-axis 3-point solve  (E -> multilinear coef tensor C)
    //   nodes m(0)=(1,0,1), m(1)=(1,0,-1), m(2)=(1,-1,0) in basis (1,y,z):
    //   C0=(b0+b1)/2, C2=(b0-b1)/2, C1=C0-b2
    // =====================================================================
    {
        int q = t / 27, g = t % 27;
        int o0 = g / 9, o1 = (g / 3) % 3, o2 = g % 3;
#define SOLVE3(BASE, S) do {                                   \
            float b0 = Csm[(BASE)];                            \
            float b1 = Csm[(BASE) + (S)];                      \
            float b2 = Csm[(BASE) + 2 * (S)];                  \
            float C0 = 0.5f * (b0 + b1);                       \
            float C2 = 0.5f * (b0 - b1);                       \
            float C1 = C0 - b2;                                \
            Csm[(BASE)] = C0;                                  \
            Csm[(BASE) + (S)] = C1;                            \
            Csm[(BASE) + 2 * (S)] = C2;                        \
        } while (0)
        if (t < 108) SOLVE3(q * 81 + o0 * 27 + o1 * 9 + o2 * 3, 1);   // axis 3
        __syncthreads();
        if (t < 108) SOLVE3(q * 81 + o0 * 27 + o1 * 9 + o2, 3);       // axis 2
        __syncthreads();
        if (t < 108) SOLVE3(q * 81 + o0 * 27 + o1 * 3 + o2, 9);       // axis 1
        __syncthreads();
        if (t < 108) SOLVE3(q * 81 + o0 * 9 + o1 * 3 + o2, 27);       // axis 0
        __syncthreads();
#undef SOLVE3
    }

    // =====================================================================
    // Phase 1: per-patch features via multilinear contraction (~320 FMA).
    //   t_q = (1, -sin aq, cos aq),  aq = 2*pi*x  (full angle)
    // =====================================================================
    if (t < PATCHES) {
        const float TWO_PI = 6.2831853071795864769f;
        float s0, c0, s1, c1, s2, c2, s3, c3;
        __sincosf(TWO_PI * px0, &s0, &c0);
        __sincosf(TWO_PI * px1, &s1, &c1);
        __sincosf(TWO_PI * px2, &s2, &c2);
        __sincosf(TWO_PI * px3, &s3, &c3);
        float t0a[3] = {1.0f, -s0, c0};
        float t1a[3] = {1.0f, -s1, c1};
        float t2a[3] = {1.0f, -s2, c2};
        float t3a[3] = {1.0f, -s3, c3};

#pragma unroll
        for (int q = 0; q < 4; q++) {
            const float* Cq = Csm + q * 81;
            float e = 0.0f;
#pragma unroll
            for (int i0 = 0; i0 < 3; i0++) {
                float acc0 = 0.0f;
#pragma unroll
                for (int i1 = 0; i1 < 3; i1++) {
                    float acc1 = 0.0f;
#pragma unroll
                    for (int i2 = 0; i2 < 3; i2++) {
                        int base = ((i0 * 3 + i1) * 3 + i2) * 3;
                        float acc2 = Cq[base]
                                   + Cq[base + 1] * t3a[1]
                                   + Cq[base + 2] * t3a[2];
                        acc1 += t2a[i2] * acc2;
                    }
                    acc0 += t1a[i1] * acc1;
                }
                e += t0a[i0] * acc0;
            }
            feat_s[t * 4 + q] = e;
        }
    }
    __syncthreads();   // feat_s ready

    // wait for fc1_w DMA (overlapped with phases 0/1)
    {
        asm volatile(
            "{\n\t.reg .pred p;\n\t"
            "WAITLP_%=:\n\t"
            "mbarrier.try_wait.parity.acquire.cta.shared::cta.b64 p, [%0], 0, 0x989680;\n\t"
            "@!p bra WAITLP_%=;\n\t}"
            :: "r"(mbar) : "memory");
    }

    // ---------------- Phase 2: FC1 from smem weights ------------------------
    {
        int neuron = t & 63;
        int part   = t >> 6;                 // constant per warp -> feat broadcast
        const float4* ws4 = (const float4*)(wsm + neuron * W_STRIDE);
        const float4* fs4 = (const float4*)feat_s;
        float ax = 0.0f, ay = 0.0f, az = 0.0f, aw2 = 0.0f;
#pragma unroll
        for (int f = part; f < FEAT / 4; f += 8) {
            float4 wv = ws4[f];
            float4 xv = fs4[f];
            ax  += wv.x * xv.x;
            ay  += wv.y * xv.y;
            az  += wv.z * xv.z;
            aw2 += wv.w * xv.w;
        }
        part_s[part * 64 + neuron] = (ax + ay) + (az + aw2);
    }
    __syncthreads();

    if (t < H1) {
        float a = fc1_b[t];
#pragma unroll
        for (int p8 = 0; p8 < 8; p8++) a += part_s[p8 * 64 + t];
        h_s[t] = fmaxf(a, 0.0f);
    }
    __syncthreads();

    // ---------------- Phase 3: FC2, one warp per output ---------------------
    if (t < NOUT * 32) {
        int o    = t >> 5;
        int lane = t & 31;
        const float* w2 = fc2_w + o * H1;
        float a = h_s[2*lane] * w2[2*lane] + h_s[2*lane + 1] * w2[2*lane + 1];
#pragma unroll
        for (int off = 16; off > 0; off >>= 1)
            a += __shfl_down_sync(0xffffffffu, a, off);
        if (lane == 0) out[b * NOUT + o] = a + fc2_b[o];
    }
}

extern "C" void kernel_launch(void* const* d_in, const int* in_sizes, int n_in,
                              void* d_out, int out_size)
{
    const float* x     = (const float*)d_in[0];
    const float* w     = (const float*)d_in[1];
    const float* fc1_w = (const float*)d_in[2];
    const float* fc1_b = (const float*)d_in[3];
    const float* fc2_w = (const float*)d_in[4];
    const float* fc2_b = (const float*)d_in[5];
    float* out = (float*)d_out;

    cudaFuncSetAttribute(fused_kernel,
                         cudaFuncAttributeMaxDynamicSharedMemorySize, SMEM_TOTAL);
    fused_kernel<<<BATCH, 512, SMEM_TOTAL>>>(x, w, fc1_w, fc1_b, fc2_w, fc2_b, out);
}

// round 12
// speedup vs baseline: 1.0450x; 1.0450x over previous
#include <cuda_runtime.h>
#include <cstdint>

#define BATCH 128
#define PATCHES 196
#define FEAT 784
#define H1 64
#define NOUT 10

#define CLUSTER 4
#define ROWS_PER_CTA (H1 / CLUSTER)

#define W_STRIDE 788
#define SMEM_W_BYTES (H1 * W_STRIDE * 4)       // 201728

#define OFF_W      0
#define OFF_FEAT   (SMEM_W_BYTES)              // 784 floats
#define OFF_PART   (OFF_FEAT + FEAT * 4)       // 8*64 floats
#define OFF_H      (OFF_PART + 8 * H1 * 4)     // 64 floats
#define OFF_M      (OFF_H + H1 * 4)            // 20 gates * 9 floats = 180
#define OFF_O      (OFF_M + 180 * 4)           // 4 obs * 256 floats (16B aligned)
#define OFF_MBAR   (OFF_O + 1024 * 4)
#define SMEM_TOTAL (OFF_MBAR + 16)

// CNOT conjugation map on Pauli digit pairs (I=0,X=1,Y=2,Z=3), idx = dc*4+dt.
// dst nibble-packed; involution. Sign - only on (1,3)<->(2,2).
#define CN_DST 0x32DC6789AB45FE10ULL
#define CN_NEG 0x0480u

__device__ __forceinline__ uint32_t saddr(const void* p) {
    return (uint32_t)__cvta_generic_to_shared(p);
}

__device__ __forceinline__ int cnot_step(int p, int shc, int sht, float& sgn) {
    int dc = (p >> shc) & 3;
    int dt = (p >> sht) & 3;
    int i  = dc * 4 + dt;
    if ((CN_NEG >> i) & 1) sgn = -sgn;
    int d = (int)((CN_DST >> (4 * i)) & 15);
    p &= ~((3 << shc) | (3 << sht));
    return p | ((d >> 2) << shc) | ((d & 3) << sht);
}

__global__ void __launch_bounds__(512) __cluster_dims__(CLUSTER, 1, 1)
fused_kernel(
    const float* __restrict__ x, const float* __restrict__ w,
    const float* __restrict__ fc1_w, const float* __restrict__ fc1_b,
    const float* __restrict__ fc2_w, const float* __restrict__ fc2_b,
    float* __restrict__ out)
{
    extern __shared__ char smem[];
    float* wsm    = (float*)(smem + OFF_W);
    float* feat_s = (float*)(smem + OFF_FEAT);
    float* part_s = (float*)(smem + OFF_PART);
    float* h_s    = (float*)(smem + OFF_H);
    float* Msm    = (float*)(smem + OFF_M);
    float* Osm    = (float*)(smem + OFF_O);
    uint32_t mbar = saddr(smem + OFF_MBAR);

    int b = blockIdx.x;
    int t = threadIdx.x;

    // ---- prefetch per-patch pixels early ----
    float px0 = 0.f, px1 = 0.f, px2 = 0.f, px3 = 0.f;
    if (t < PATCHES) {
        int i = t / 14, j = t % 14;
        const float* xb = x + b * FEAT;
        px0 = xb[(2*i)  *28 + 2*j    ];
        px1 = xb[(2*i)  *28 + 2*j + 1];
        px2 = xb[(2*i+1)*28 + 2*j    ];
        px3 = xb[(2*i+1)*28 + 2*j + 1];
    }

    // ---- per-gate 3x3 Pauli rotation matrices (one thread per gate) ----
    // Folded U = Ry(t3)*Rz(t2)*Ry(t1); quat (w,x,y,z)=(ar,bi,-br,ai);
    // c' = M c implements O <- U+ O U  (verified vs direct Ry/Rz conjugation).
    if (t < 20) {
        int l = t >> 2, q = t & 3;
        float c1, s1, c2, s2, c3, s3;
        __sincosf(0.5f * w[12*l + q],     &s1, &c1);
        __sincosf(0.5f * w[12*l + 4 + q], &s2, &c2);
        __sincosf(0.5f * w[12*l + 8 + q], &s3, &c3);
        float ar =  c2 * (c3*c1 - s3*s1);
        float ai = -s2 * (c3*c1 + s3*s1);
        float br =  c2 * (s3*c1 + c3*s1);
        float bi =  s2 * (c3*s1 - s3*c1);
        float W = ar, X = bi, Y = -br, Z = ai;
        float* M = Msm + t * 9;
        M[0] = 1.f - 2.f*(Y*Y + Z*Z);  M[1] = 2.f*(X*Y - W*Z);  M[2] = 2.f*(X*Z + W*Y);
        M[3] = 2.f*(X*Y + W*Z);  M[4] = 1.f - 2.f*(X*X + Z*Z);  M[5] = 2.f*(Y*Z - W*X);
        M[6] = 2.f*(X*Z - W*Y);  M[7] = 2.f*(Y*Z + W*X);  M[8] = 1.f - 2.f*(X*X + Y*Y);
    } else if (t == 511) {
        asm volatile("mbarrier.init.shared.b64 [%0], 1;" :: "r"(mbar) : "memory");
    }

    // ---- init O[q] = Z_q  (digit 3 at position q; p = d0*64+d1*16+d2*4+d3) ----
    {
        int e0 = t, e1 = t + 512;
        Osm[e0] = ((e0 & 255) == 3 * (64 >> (2 * (e0 >> 8)))) ? 1.0f : 0.0f;
        Osm[e1] = ((e1 & 255) == 3 * (64 >> (2 * (e1 >> 8)))) ? 1.0f : 0.0f;
    }
    __syncthreads();

    // ---- cluster barrier before multicast DMA ----
    asm volatile("barrier.cluster.arrive.aligned;" ::: "memory");
    asm volatile("barrier.cluster.wait.aligned;"   ::: "memory");

    if (t == 511) {
        uint32_t rank;
        asm("mov.u32 %0, %%cluster_ctarank;" : "=r"(rank));
        asm volatile("mbarrier.arrive.expect_tx.shared.b64 _, [%0], %1;"
                     :: "r"(mbar), "r"((uint32_t)(H1 * 3136u)) : "memory");
        const uint16_t mask = (1u << CLUSTER) - 1u;
        int row0 = rank * ROWS_PER_CTA;
        for (int n = row0; n < row0 + ROWS_PER_CTA; n++) {
            uint32_t dst = saddr(wsm + n * W_STRIDE);
            const float* src = fc1_w + n * FEAT;
            asm volatile(
                "cp.async.bulk.shared::cluster.global.mbarrier::complete_tx::bytes"
                ".multicast::cluster [%0], [%1], %2, [%3], %4;"
                :: "r"(dst), "l"(src), "r"(3136u), "r"(mbar), "h"(mask) : "memory");
        }
    }

    // =====================================================================
    // Phase 0: Heisenberg backprop of Z_q through the circuit (Pauli basis).
    // Conj order = reverse circuit: L4 gates, ring, L3, ring, ..., ring, L0.
    // =====================================================================
    {
        const int Sq_tab[4]    = {64, 16, 4, 1};
        const int OS_tab[4][3] = {{16,4,1},{64,4,1},{64,16,1},{64,16,4}};

#pragma unroll
        for (int step = 0; step < 9; step++) {
            // steps 0,2,4,6,8 -> gate layers l = 4,3,2,1,0; odd steps -> ring
            if ((step & 1) == 0) {
                int l = 4 - (step >> 1);
#pragma unroll
                for (int q = 0; q < 4; q++) {
                    if (t < 256) {
                        int obs = t >> 6, g = t & 63;
                        int base = obs * 256
                                 + (g >> 4)       * OS_tab[q][0]
                                 + ((g >> 2) & 3) * OS_tab[q][1]
                                 + (g & 3)        * OS_tab[q][2];
                        int S = Sq_tab[q];
                        const float* M = Msm + (l * 4 + q) * 9;
                        float cx = Osm[base + S];
                        float cy = Osm[base + 2*S];
                        float cz = Osm[base + 3*S];
                        Osm[base + S]   = M[0]*cx + M[1]*cy + M[2]*cz;
                        Osm[base + 2*S] = M[3]*cx + M[4]*cy + M[5]*cz;
                        Osm[base + 3*S] = M[6]*cx + M[7]*cy + M[8]*cz;
                    }
                    __syncthreads();
                }
            } else {
                // ring conj = conj by C30,C23,C12,C01 composed into one gather:
                // walk F01 -> F12 -> F23 -> F30 accumulating signs.
                int e0 = t, e1 = t + 512;
                float g0 = 1.f, g1 = 1.f;
                int p0 = e0 & 255, p1 = e1 & 255;
                p0 = cnot_step(p0, 6, 4, g0);  p1 = cnot_step(p1, 6, 4, g1);
                p0 = cnot_step(p0, 4, 2, g0);  p1 = cnot_step(p1, 4, 2, g1);
                p0 = cnot_step(p0, 2, 0, g0);  p1 = cnot_step(p1, 2, 0, g1);
                p0 = cnot_step(p0, 0, 6, g0);  p1 = cnot_step(p1, 0, 6, g1);
                float v0 = g0 * Osm[(e0 & ~255) | p0];
                float v1 = g1 * Osm[(e1 & ~255) | p1];
                __syncthreads();
                Osm[e0] = v0;
                Osm[e1] = v1;
                __syncthreads();
            }
        }
    }

    // =====================================================================
    // Phase 1: per-patch contraction.  t_q = (1, -sin a, cos a) on digits
    // (I, Y, Z) = (0, 2, 3); X strings vanish.  float4 covers digit-3 axis.
    // =====================================================================
    if (t < PATCHES) {
        const float TWO_PI = 6.2831853071795864769f;
        float s0, c0, s1, c1, s2, c2, s3, c3;
        __sincosf(TWO_PI * px0, &s0, &c0);
        __sincosf(TWO_PI * px1, &s1, &c1);
        __sincosf(TWO_PI * px2, &s2, &c2);
        __sincosf(TWO_PI * px3, &s3, &c3);
        float T0[3] = {1.0f, -s0, c0};
        float T1[3] = {1.0f, -s1, c1};
        float T2[3] = {1.0f, -s2, c2};
        const float T3y = -s3, T3z = c3;
        const int dig[3] = {0, 2, 3};

#pragma unroll
        for (int q = 0; q < 4; q++) {
            const float4* Oq4 = (const float4*)(Osm + q * 256);
            float e = 0.0f;
#pragma unroll
            for (int i0 = 0; i0 < 3; i0++) {
                float acc0 = 0.0f;
#pragma unroll
                for (int i1 = 0; i1 < 3; i1++) {
                    float acc1 = 0.0f;
#pragma unroll
                    for (int i2 = 0; i2 < 3; i2++) {
                        float4 wv = Oq4[dig[i0]*16 + dig[i1]*4 + dig[i2]];
                        float acc2 = wv.x + wv.z * T3y + wv.w * T3z;
                        acc1 += T2[i2] * acc2;
                    }
                    acc0 += T1[i1] * acc1;
                }
                e += T0[i0] * acc0;
            }
            feat_s[t * 4 + q] = e;
        }
    }
    __syncthreads();   // feat_s ready

    // wait for fc1_w DMA (overlapped with phases 0/1)
    asm volatile(
        "{\n\t.reg .pred p;\n\t"
        "WAITLP_%=:\n\t"
        "mbarrier.try_wait.parity.acquire.cta.shared::cta.b64 p, [%0], 0, 0x989680;\n\t"
        "@!p bra WAITLP_%=;\n\t}"
        :: "r"(mbar) : "memory");

    // ---------------- Phase 2: FC1 from smem weights ------------------------
    {
        int neuron = t & 63;
        int part   = t >> 6;                 // constant per warp -> feat broadcast
        const float4* ws4 = (const float4*)(wsm + neuron * W_STRIDE);
        const float4* fs4 = (const float4*)feat_s;
        float ax = 0.0f, ay = 0.0f, az = 0.0f, aw2 = 0.0f;
#pragma unroll
        for (int f = part; f < FEAT / 4; f += 8) {
            float4 wv = ws4[f];
            float4 xv = fs4[f];
            ax  += wv.x * xv.x;
            ay  += wv.y * xv.y;
            az  += wv.z * xv.z;
            aw2 += wv.w * xv.w;
        }
        part_s[part * 64 + neuron] = (ax + ay) + (az + aw2);
    }
    __syncthreads();

    if (t < H1) {
        float a = fc1_b[t];
#pragma unroll
        for (int p8 = 0; p8 < 8; p8++) a += part_s[p8 * 64 + t];
        h_s[t] = fmaxf(a, 0.0f);
    }
    __syncthreads();

    // ---------------- Phase 3: FC2, one warp per output ---------------------
    if (t < NOUT * 32) {
        int o    = t >> 5;
        int lane = t & 31;
        const float* w2 = fc2_w + o * H1;
        float a = h_s[2*lane] * w2[2*lane] + h_s[2*lane + 1] * w2[2*lane + 1];
#pragma unroll
        for (int off = 16; off > 0; off >>= 1)
            a += __shfl_down_sync(0xffffffffu, a, off);
        if (lane == 0) out[b * NOUT + o] = a + fc2_b[o];
    }
}

extern "C" void kernel_launch(void* const* d_in, const int* in_sizes, int n_in,
                              void* d_out, int out_size)
{
    const float* x     = (const float*)d_in[0];
    const float* w     = (const float*)d_in[1];
    const float* fc1_w = (const float*)d_in[2];
    const float* fc1_b = (const float*)d_in[3];
    const float* fc2_w = (const float*)d_in[4];
    const float* fc2_b = (const float*)d_in[5];
    float* out = (float*)d_out;

    cudaFuncSetAttribute(fused_kernel,
                         cudaFuncAttributeMaxDynamicSharedMemorySize, SMEM_TOTAL);
    fused_kernel<<<BATCH, 512, SMEM_TOTAL>>>(x, w, fc1_w, fc1_b, fc2_w, fc2_b, out);
}

// round 13
// speedup vs baseline: 1.0476x; 1.0025x over previous
#include <cuda_runtime.h>
#include <cstdint>

#define BATCH 128
#define PATCHES 196
#define FEAT 784
#define H1 64
#define NOUT 10

#define CLUSTER 4
#define ROWS_PER_CTA (H1 / CLUSTER)

#define W_STRIDE 788
#define SMEM_W_BYTES (H1 * W_STRIDE * 4)       // 201728

#define OFF_W      0
#define OFF_FEAT   (SMEM_W_BYTES)              // 784 floats
#define OFF_PART   (OFF_FEAT + FEAT * 4)       // 8*64 floats
#define OFF_H      (OFF_PART + 8 * H1 * 4)     // 64 floats
#define OFF_M      (OFF_H + H1 * 4)            // 20 gates * 9 floats = 180
#define OFF_O0     (OFF_M + 180 * 4)           // 1024 floats (16B aligned)
#define OFF_O1     (OFF_O0 + 1024 * 4)         // 1024 floats
#define OFF_RMAP   (OFF_O1 + 1024 * 4)         // 256 ints
#define OFF_MBAR   (OFF_RMAP + 256 * 4)
#define SMEM_TOTAL (OFF_MBAR + 16)

// CNOT conjugation map on Pauli digit pairs (I=0,X=1,Y=2,Z=3), idx = dc*4+dt.
// dst nibble-packed; involution. Sign - only on (1,3)<->(2,2).
#define CN_DST 0x32DC6789AB45FE10ULL
#define CN_NEG 0x0480u

__device__ __forceinline__ uint32_t saddr(const void* p) {
    return (uint32_t)__cvta_generic_to_shared(p);
}

__device__ __forceinline__ int cnot_step(int p, int shc, int sht, int& neg) {
    int dc = (p >> shc) & 3;
    int dt = (p >> sht) & 3;
    int i  = dc * 4 + dt;
    neg ^= (CN_NEG >> i) & 1;
    int d = (int)((CN_DST >> (4 * i)) & 15);
    p &= ~((3 << shc) | (3 << sht));
    return p | ((d >> 2) << shc) | ((d & 3) << sht);
}

__global__ void __launch_bounds__(512) __cluster_dims__(CLUSTER, 1, 1)
fused_kernel(
    const float* __restrict__ x, const float* __restrict__ w,
    const float* __restrict__ fc1_w, const float* __restrict__ fc1_b,
    const float* __restrict__ fc2_w, const float* __restrict__ fc2_b,
    float* __restrict__ out)
{
    extern __shared__ char smem[];
    float* wsm    = (float*)(smem + OFF_W);
    float* feat_s = (float*)(smem + OFF_FEAT);
    float* part_s = (float*)(smem + OFF_PART);
    float* h_s    = (float*)(smem + OFF_H);
    float* Msm    = (float*)(smem + OFF_M);
    float* O0     = (float*)(smem + OFF_O0);
    float* O1     = (float*)(smem + OFF_O1);
    int*   rmap   = (int*)  (smem + OFF_RMAP);
    uint32_t mbar = saddr(smem + OFF_MBAR);

    int b = blockIdx.x;
    int t = threadIdx.x;

    // ---- prefetch per-patch pixels early (2 threads per patch) ----
    float px0 = 0.f, px1 = 0.f, px2 = 0.f, px3 = 0.f;
    int tp = t >> 1;
    if (tp < PATCHES) {
        int i = tp / 14, j = tp % 14;
        const float* xb = x + b * FEAT;
        px0 = xb[(2*i)  *28 + 2*j    ];
        px1 = xb[(2*i)  *28 + 2*j + 1];
        px2 = xb[(2*i+1)*28 + 2*j    ];
        px3 = xb[(2*i+1)*28 + 2*j + 1];
    }

    // ---- per-gate 3x3 Pauli rotation matrices (one thread per gate) ----
    // Folded U = Ry(t3)*Rz(t2)*Ry(t1); quat (w,x,y,z)=(ar,bi,-br,ai).
    if (t < 20) {
        int l = t >> 2, q = t & 3;
        float c1, s1, c2, s2, c3, s3;
        __sincosf(0.5f * w[12*l + q],     &s1, &c1);
        __sincosf(0.5f * w[12*l + 4 + q], &s2, &c2);
        __sincosf(0.5f * w[12*l + 8 + q], &s3, &c3);
        float ar =  c2 * (c3*c1 - s3*s1);
        float ai = -s2 * (c3*c1 + s3*s1);
        float br =  c2 * (s3*c1 + c3*s1);
        float bi =  s2 * (c3*s1 - s3*c1);
        float W = ar, X = bi, Y = -br, Z = ai;
        float* M = Msm + t * 9;
        M[0] = 1.f - 2.f*(Y*Y + Z*Z);  M[1] = 2.f*(X*Y - W*Z);  M[2] = 2.f*(X*Z + W*Y);
        M[3] = 2.f*(X*Y + W*Z);  M[4] = 1.f - 2.f*(X*X + Z*Z);  M[5] = 2.f*(Y*Z - W*X);
        M[6] = 2.f*(X*Z - W*Y);  M[7] = 2.f*(Y*Z + W*X);  M[8] = 1.f - 2.f*(X*X + Y*Y);
    } else if (t == 511) {
        asm volatile("mbarrier.init.shared.b64 [%0], 1;" :: "r"(mbar) : "memory");
    }

    // ---- ring map (dest -> signed source), same walk as verified R11 ring ----
    if (t < 256) {
        int neg = 0;
        int p = t;
        p = cnot_step(p, 6, 4, neg);
        p = cnot_step(p, 4, 2, neg);
        p = cnot_step(p, 2, 0, neg);
        p = cnot_step(p, 0, 6, neg);
        rmap[t] = p | (neg << 8);
    }

    // ---- init O[q] = Z_q into buf0 ----
    {
        int e0 = t, e1 = t + 512;
        O0[e0] = ((e0 & 255) == 3 * (64 >> (2 * (e0 >> 8)))) ? 1.0f : 0.0f;
        O0[e1] = ((e1 & 255) == 3 * (64 >> (2 * (e1 >> 8)))) ? 1.0f : 0.0f;
    }
    __syncthreads();

    // ---- cluster barrier before multicast DMA ----
    asm volatile("barrier.cluster.arrive.aligned;" ::: "memory");
    asm volatile("barrier.cluster.wait.aligned;"   ::: "memory");

    if (t == 511) {
        uint32_t rank;
        asm("mov.u32 %0, %%cluster_ctarank;" : "=r"(rank));
        asm volatile("mbarrier.arrive.expect_tx.shared.b64 _, [%0], %1;"
                     :: "r"(mbar), "r"((uint32_t)(H1 * 3136u)) : "memory");
        const uint16_t mask = (1u << CLUSTER) - 1u;
        int row0 = rank * ROWS_PER_CTA;
        for (int n = row0; n < row0 + ROWS_PER_CTA; n++) {
            uint32_t dst = saddr(wsm + n * W_STRIDE);
            const float* src = fc1_w + n * FEAT;
            asm volatile(
                "cp.async.bulk.shared::cluster.global.mbarrier::complete_tx::bytes"
                ".multicast::cluster [%0], [%1], %2, [%3], %4;"
                :: "r"(dst), "l"(src), "r"(3136u), "r"(mbar), "h"(mask) : "memory");
        }
    }

    // =====================================================================
    // Phase 0: Heisenberg backprop, double-buffered, ring folded into the
    // first gate pass of layers 3..0. Pass k: layer l=4-(k>>2), axis q=k&3.
    // One __syncthreads per pass (20 total).
    // =====================================================================
    {
        const int Sq_tab[4]    = {64, 16, 4, 1};
        const int OS_tab[4][3] = {{16,4,1},{64,4,1},{64,16,1},{64,16,4}};

#pragma unroll
        for (int k = 0; k < 20; k++) {
            const int l = 4 - (k >> 2);
            const int q = k & 3;
            const bool ringp = (q == 0) && (l < 4);
            if (t < 256) {
                const float* rb = (k & 1) ? O1 : O0;
                float*       wb = (k & 1) ? O0 : O1;
                int obs = t >> 6, g = t & 63;
                int off = (g >> 4)       * OS_tab[q][0]
                        + ((g >> 2) & 3) * OS_tab[q][1]
                        + (g & 3)        * OS_tab[q][2];   // local (within 256)
                int S = Sq_tab[q];
                int ob = obs * 256;
                float s0, s1, s2, s3;
                if (ringp) {
                    int m0 = rmap[off];
                    int m1 = rmap[off + S];
                    int m2 = rmap[off + 2*S];
                    int m3 = rmap[off + 3*S];
                    s0 = rb[ob + (m0 & 255)]; if (m0 & 256) s0 = -s0;
                    s1 = rb[ob + (m1 & 255)]; if (m1 & 256) s1 = -s1;
                    s2 = rb[ob + (m2 & 255)]; if (m2 & 256) s2 = -s2;
                    s3 = rb[ob + (m3 & 255)]; if (m3 & 256) s3 = -s3;
                } else {
                    s0 = rb[ob + off];
                    s1 = rb[ob + off + S];
                    s2 = rb[ob + off + 2*S];
                    s3 = rb[ob + off + 3*S];
                }
                const float* M = Msm + (l * 4 + q) * 9;
                wb[ob + off]       = s0;
                wb[ob + off + S]   = M[0]*s1 + M[1]*s2 + M[2]*s3;
                wb[ob + off + 2*S] = M[3]*s1 + M[4]*s2 + M[5]*s3;
                wb[ob + off + 3*S] = M[6]*s1 + M[7]*s2 + M[8]*s3;
            }
            __syncthreads();
        }
    }
    // 20 passes (even) -> final tensor in O0.

    // =====================================================================
    // Phase 1: per-patch contraction, 2 threads per patch (2 obs each).
    // t_q = (1, -sin a, cos a) on digits (I,Y,Z)=(0,2,3); X strings vanish.
    // =====================================================================
    if (tp < PATCHES) {
        int half = t & 1;
        const float TWO_PI = 6.2831853071795864769f;
        float s0, c0, s1, c1, s2, c2, s3, c3;
        __sincosf(TWO_PI * px0, &s0, &c0);
        __sincosf(TWO_PI * px1, &s1, &c1);
        __sincosf(TWO_PI * px2, &s2, &c2);
        __sincosf(TWO_PI * px3, &s3, &c3);
        float T0[3] = {1.0f, -s0, c0};
        float T1[3] = {1.0f, -s1, c1};
        float T2[3] = {1.0f, -s2, c2};
        const float T3y = -s3, T3z = c3;
        const int dig[3] = {0, 2, 3};

#pragma unroll
        for (int qq = 0; qq < 2; qq++) {
            int q = half * 2 + qq;
            const float4* Oq4 = (const float4*)(O0 + q * 256);
            float e = 0.0f;
#pragma unroll
            for (int i0 = 0; i0 < 3; i0++) {
                float acc0 = 0.0f;
#pragma unroll
                for (int i1 = 0; i1 < 3; i1++) {
                    float acc1 = 0.0f;
#pragma unroll
                    for (int i2 = 0; i2 < 3; i2++) {
                        float4 wv = Oq4[dig[i0]*16 + dig[i1]*4 + dig[i2]];
                        float acc2 = wv.x + wv.z * T3y + wv.w * T3z;
                        acc1 += T2[i2] * acc2;
                    }
                    acc0 += T1[i1] * acc1;
                }
                e += T0[i0] * acc0;
            }
            feat_s[tp * 4 + q] = e;
        }
    }
    __syncthreads();   // feat_s ready

    // wait for fc1_w DMA (overlapped with phases 0/1)
    asm volatile(
        "{\n\t.reg .pred p;\n\t"
        "WAITLP_%=:\n\t"
        "mbarrier.try_wait.parity.acquire.cta.shared::cta.b64 p, [%0], 0, 0x989680;\n\t"
        "@!p bra WAITLP_%=;\n\t}"
        :: "r"(mbar) : "memory");

    // ---------------- Phase 2: FC1 from smem weights ------------------------
    {
        int neuron = t & 63;
        int part   = t >> 6;                 // constant per warp -> feat broadcast
        const float4* ws4 = (const float4*)(wsm + neuron * W_STRIDE);
        const float4* fs4 = (const float4*)feat_s;
        float ax = 0.0f, ay = 0.0f, az = 0.0f, aw2 = 0.0f;
#pragma unroll
        for (int f = part; f < FEAT / 4; f += 8) {
            float4 wv = ws4[f];
            float4 xv = fs4[f];
            ax  += wv.x * xv.x;
            ay  += wv.y * xv.y;
            az  += wv.z * xv.z;
            aw2 += wv.w * xv.w;
        }
        part_s[part * 64 + neuron] = (ax + ay) + (az + aw2);
    }
    __syncthreads();

    if (t < H1) {
        float a = fc1_b[t];
#pragma unroll
        for (int p8 = 0; p8 < 8; p8++) a += part_s[p8 * 64 + t];
        h_s[t] = fmaxf(a, 0.0f);
    }
    __syncthreads();

    // ---------------- Phase 3: FC2, one warp per output ---------------------
    if (t < NOUT * 32) {
        int o    = t >> 5;
        int lane = t & 31;
        const float* w2 = fc2_w + o * H1;
        float a = h_s[2*lane] * w2[2*lane] + h_s[2*lane + 1] * w2[2*lane + 1];
#pragma unroll
        for (int off = 16; off > 0; off >>= 1)
            a += __shfl_down_sync(0xffffffffu, a, off);
        if (lane == 0) out[b * NOUT + o] = a + fc2_b[o];
    }
}

extern "C" void kernel_launch(void* const* d_in, const int* in_sizes, int n_in,
                              void* d_out, int out_size)
{
    const float* x     = (const float*)d_in[0];
    const float* w     = (const float*)d_in[1];
    const float* fc1_w = (const float*)d_in[2];
    const float* fc1_b = (const float*)d_in[3];
    const float* fc2_w = (const float*)d_in[4];
    const float* fc2_b = (const float*)d_in[5];
    float* out = (float*)d_out;

    cudaFuncSetAttribute(fused_kernel,
                         cudaFuncAttributeMaxDynamicSharedMemorySize, SMEM_TOTAL);
    fused_kernel<<<BATCH, 512, SMEM_TOTAL>>>(x, w, fc1_w, fc1_b, fc2_w, fc2_b, out);
}